// round 9
// baseline (speedup 1.0000x reference)
#include <cuda_runtime.h>
#include <cstdint>

// Problem constants
#define NLAT   8192
#define NSMP   2048
#define ES     64
#define EA     32
#define FARK   64
#define TPB    256
#define SCHUNK (NSMP / TPB)     // 8 sample chunks
#define NSL_S  45               // latent slices, states
#define NSL_A  25               // latent slices, actions
#define NSL_Z  4                // size-loss block rows
// 8*(45+25+4) = 592 blocks = exactly 2 waves at occupancy 2
#define FLT_BIG 3.402823466e+38f
#define NPOST  16               // post kernel blocks (8 chunks x 2 tensors)

// ---------------- scratch (device globals; no allocation allowed) ----------
__device__ float g_pt4_s[NSL_S * NSMP * 4];   // [slice][sample][4]
__device__ float g_pt4_a[NSL_A * NSMP * 4];
__device__ float g_tail[2][NSMP];
__device__ float g_size_part[NSL_Z * 8];
__device__ float g_red[NPOST];
__device__ int   g_done1, g_done2;

// branchless sorted insert: keep m0<=m1<=m2<=m3 smallest
__device__ __forceinline__ void ins4(float d, float& m0, float& m1, float& m2, float& m3) {
    float lo, hi;
    lo = fminf(m0, d);  hi = fmaxf(m0, d);  m0 = lo;
    lo = fminf(m1, hi); hi = fmaxf(m1, hi); m1 = lo;
    lo = fminf(m2, hi); hi = fmaxf(m2, hi); m2 = lo;
    m3 = fminf(m3, hi);
}

// ---------------- size loss partials (runs inside the cov launch) ----------
template<int E>
__device__ __forceinline__ float size_accum(const float* __restrict__ lat, int r0, int nrows, int tid) {
    float acc = 0.0f;
    for (int r = r0 + tid; r < r0 + nrows; r += TPB) {
        const float* row = lat + r * E;
        float a0 = 0.f, a1 = 0.f, a2 = 0.f, a3 = 0.f;
        #pragma unroll
        for (int k = 0; k < E; k += 4) {
            float4 v = *(const float4*)(row + k);
            a0 += fabsf(v.x); a1 += fabsf(v.y); a2 += fabsf(v.z); a3 += fabsf(v.w);
        }
        float n = (a0 + a1) + (a2 + a3);
        float viol = fmaxf(n - 1.0f, 0.0f);
        acc += viol * viol;
    }
    return acc;
}

__device__ void size_body(const float* __restrict__ lat_s,
                          const float* __restrict__ lat_a, int b, float* red) {
    const int tid = threadIdx.x;
    float acc = (b < 16) ? size_accum<ES>(lat_s, b * 512, 512, tid)
                         : size_accum<EA>(lat_a, (b - 16) * 512, 512, tid);
    red[tid] = acc;
    __syncthreads();
    for (int st = TPB / 2; st > 0; st >>= 1) {
        if (tid < st) red[tid] += red[tid + st];
        __syncthreads();
    }
    if (tid == 0) g_size_part[b] = red[0];
}

// ---------------- coverage partial top-4 (FFMA-imm, latent-pair unroll) ----
// d  = fmaf(lat, -0.5, q*0.5);  acc = fmaf(|d|, 2.0, acc)  -> FFMA-imm rt=1
// Exact rescale: fl((q-l)/2)*2 == fl(q-l); bit-identical to FADD chain.
template<int E, int TN, int NSL>
__device__ __forceinline__ void cov_body(const float* __restrict__ samples,
                                         const float* __restrict__ latents,
                                         int slice, float* tile, float* out4) {
    const int tid = threadIdx.x;
    const int s   = blockIdx.x * TPB + tid;

    constexpr int base = NLAT / NSL;
    constexpr int rem  = NLAT % NSL;
    const int start = slice * base + (slice < rem ? slice : rem);
    const int len   = base + (slice < rem ? 1 : 0);

    float qh[E];
    #pragma unroll
    for (int k = 0; k < E; k += 4) {
        float4 v = *(const float4*)(samples + s * E + k);
        qh[k] = 0.5f * v.x; qh[k + 1] = 0.5f * v.y;
        qh[k + 2] = 0.5f * v.z; qh[k + 3] = 0.5f * v.w;
    }

    float m0 = FLT_BIG, m1 = FLT_BIG, m2 = FLT_BIG, m3 = FLT_BIG;

    for (int t0 = 0; t0 < len; t0 += TN) {
        const int tn = (len - t0 < TN) ? (len - t0) : TN;
        __syncthreads();
        const float4* src = (const float4*)(latents + (start + t0) * E);
        float4* dst = (float4*)tile;
        for (int i = tid; i < tn * (E / 4); i += TPB) dst[i] = src[i];
        __syncthreads();

        int n = 0;
        #pragma unroll 1
        for (; n + 2 <= tn; n += 2) {
            const float4* lrA = (const float4*)(tile + n * E);
            const float4* lrB = (const float4*)(tile + (n + 1) * E);
            float a0 = 0.f, a1 = 0.f, a2 = 0.f, a3 = 0.f;
            float b0 = 0.f, b1 = 0.f, b2 = 0.f, b3 = 0.f;
            #pragma unroll
            for (int k = 0; k < E / 4; k++) {
                float4 va = lrA[k];
                float d0 = fmaf(va.x, -0.5f, qh[4 * k]);
                float d1 = fmaf(va.y, -0.5f, qh[4 * k + 1]);
                float d2 = fmaf(va.z, -0.5f, qh[4 * k + 2]);
                float d3 = fmaf(va.w, -0.5f, qh[4 * k + 3]);
                a0 = fmaf(fabsf(d0), 2.0f, a0);
                a1 = fmaf(fabsf(d1), 2.0f, a1);
                a2 = fmaf(fabsf(d2), 2.0f, a2);
                a3 = fmaf(fabsf(d3), 2.0f, a3);
                float4 vb = lrB[k];
                float e0 = fmaf(vb.x, -0.5f, qh[4 * k]);
                float e1 = fmaf(vb.y, -0.5f, qh[4 * k + 1]);
                float e2 = fmaf(vb.z, -0.5f, qh[4 * k + 2]);
                float e3 = fmaf(vb.w, -0.5f, qh[4 * k + 3]);
                b0 = fmaf(fabsf(e0), 2.0f, b0);
                b1 = fmaf(fabsf(e1), 2.0f, b1);
                b2 = fmaf(fabsf(e2), 2.0f, b2);
                b3 = fmaf(fabsf(e3), 2.0f, b3);
            }
            ins4((a0 + a1) + (a2 + a3), m0, m1, m2, m3);
            ins4((b0 + b1) + (b2 + b3), m0, m1, m2, m3);
        }
        if (n < tn) {   // odd epilogue
            const float4* lr = (const float4*)(tile + n * E);
            float a0 = 0.f, a1 = 0.f, a2 = 0.f, a3 = 0.f;
            #pragma unroll
            for (int k = 0; k < E / 4; k++) {
                float4 v = lr[k];
                float d0 = fmaf(v.x, -0.5f, qh[4 * k]);
                float d1 = fmaf(v.y, -0.5f, qh[4 * k + 1]);
                float d2 = fmaf(v.z, -0.5f, qh[4 * k + 2]);
                float d3 = fmaf(v.w, -0.5f, qh[4 * k + 3]);
                a0 = fmaf(fabsf(d0), 2.0f, a0);
                a1 = fmaf(fabsf(d1), 2.0f, a1);
                a2 = fmaf(fabsf(d2), 2.0f, a2);
                a3 = fmaf(fabsf(d3), 2.0f, a3);
            }
            ins4((a0 + a1) + (a2 + a3), m0, m1, m2, m3);
        }
    }
    *(float4*)(out4 + (slice * NSMP + s) * 4) = make_float4(m0, m1, m2, m3);
}

// grid: (SCHUNK, NSL_S + NSL_A + NSL_Z)
__global__ void __launch_bounds__(TPB, 2)
cov_partial_kernel(const float* __restrict__ smp_s, const float* __restrict__ lat_s,
                   const float* __restrict__ smp_a, const float* __restrict__ lat_a) {
    __shared__ __align__(16) float tile[8192];   // 32 KB
    const int y = blockIdx.y;
    if (y < NSL_S)
        cov_body<ES, 128, NSL_S>(smp_s, lat_s, y, tile, g_pt4_s);
    else if (y < NSL_S + NSL_A)
        cov_body<EA, 256, NSL_A>(smp_a, lat_a, y - NSL_S, tile, g_pt4_a);
    else
        size_body(lat_s, lat_a, (y - NSL_S - NSL_A) * 8 + blockIdx.x, tile);
}

// ---------------- fused post: merge + rank + combine in ONE kernel ---------
// grid (SCHUNK, 2) = 16 blocks (always co-resident on 148 SMs -> spin-safe).
// Phase 1: merge slice partials -> tail/sq per sample (thread-owned).
// Global barrier (atomic arrive + volatile spin).
// Phase 2: stable rank counts vs all 2048 tails (smem), select, block-reduce.
// Phase 3: last-arriving block does fixed-order final sum + counter reset.
__global__ void post_kernel(float* __restrict__ out) {
    __shared__ __align__(16) float tl[NSMP];
    __shared__ float red[TPB];
    const int sel = blockIdx.y;
    const int tid = threadIdx.x;
    const int s   = blockIdx.x * TPB + tid;

    // ---- phase 1: merge ----
    const int nsl = sel ? NSL_A : NSL_S;
    const float* base = sel ? g_pt4_a : g_pt4_s;
    float m0 = FLT_BIG, m1 = FLT_BIG, m2 = FLT_BIG, m3 = FLT_BIG;
    for (int k = 0; k < nsl; k++) {
        float4 v = *(const float4*)(base + ((size_t)k * NSMP + s) * 4);
        ins4(v.x, m0, m1, m2, m3);
        ins4(v.y, m0, m1, m2, m3);
        ins4(v.z, m0, m1, m2, m3);
        ins4(v.w, m0, m1, m2, m3);
    }
    const float tail = 0.25f * ((m0 + m1) + (m2 + m3));
    const float sq   = (m0 * m0 + m1 * m1) + (m2 * m2 + m3 * m3);
    g_tail[sel][s] = tail;
    __threadfence();
    __syncthreads();
    if (tid == 0) {
        atomicAdd(&g_done1, 1);
        while (*(volatile int*)&g_done1 < NPOST) { }
    }
    __syncthreads();
    __threadfence();

    // ---- phase 2: rank + select ----
    for (int i = tid; i < NSMP; i += TPB) tl[i] = g_tail[sel][i];
    __syncthreads();
    const int ti = __float_as_int(tail);   // positive floats: int order == fp order
    int cnt = 0;
    #pragma unroll 4
    for (int j = 0; j < NSMP; j += 4) {
        float4 v = *(const float4*)(tl + j);
        cnt += (__float_as_int(v.x) > ti) || (__float_as_int(v.x) == ti && (j)     < s);
        cnt += (__float_as_int(v.y) > ti) || (__float_as_int(v.y) == ti && (j + 1) < s);
        cnt += (__float_as_int(v.z) > ti) || (__float_as_int(v.z) == ti && (j + 2) < s);
        cnt += (__float_as_int(v.w) > ti) || (__float_as_int(v.w) == ti && (j + 3) < s);
    }
    red[tid] = (cnt < FARK) ? sq : 0.0f;
    __syncthreads();
    for (int st = TPB / 2; st > 0; st >>= 1) {
        if (tid < st) red[tid] += red[tid + st];
        __syncthreads();
    }

    // ---- phase 3: last block combines (fixed-order -> deterministic) ----
    if (tid == 0) {
        g_red[sel * SCHUNK + blockIdx.x] = red[0];
        __threadfence();
        if (atomicAdd(&g_done2, 1) == NPOST - 1) {
            float r = 0.f;
            #pragma unroll
            for (int b = 0; b < NPOST; b++) r += g_red[b];
            float ss = 0.f, sa = 0.f;
            #pragma unroll
            for (int b = 0; b < 16; b++)  ss += g_size_part[b];
            #pragma unroll
            for (int b = 16; b < 32; b++) sa += g_size_part[b];
            out[0] = ss / (float)NLAT + sa / (float)NLAT + r / (float)(FARK * 4);
            g_done1 = 0;              // reset for next graph replay
            g_done2 = 0;
            __threadfence();
        }
    }
}

// ---------------- launch ----------------------------------------------------
extern "C" void kernel_launch(void* const* d_in, const int* in_sizes, int n_in,
                              void* d_out, int out_size) {
    const float* lat_s = (const float*)d_in[0];   // latent_states   [8192,64]
    const float* lat_a = (const float*)d_in[1];   // latent_actions  [8192,32]
    const float* smp_s = (const float*)d_in[2];   // state samples   [2048,64]
    const float* smp_a = (const float*)d_in[3];   // action samples  [2048,32]
    float* out = (float*)d_out;

    cov_partial_kernel<<<dim3(SCHUNK, NSL_S + NSL_A + NSL_Z), TPB>>>(smp_s, lat_s, smp_a, lat_a);
    post_kernel<<<dim3(SCHUNK, 2), TPB>>>(out);
}